// round 1
// baseline (speedup 1.0000x reference)
#include <cuda_runtime.h>
#include <cuda_bf16.h>

// Problem constants
#define BB   64
#define LL   512
#define HH   256
#define HD   128
#define NG   512            // 4 * HD gates
#define M_TOT (BB*LL)       // 32768 cells / rows

// 64 MB scratch for precomputed input gates: g_pre[m][n] = feats[m]@W_ih^T + b_ih + b_hh
__device__ float g_pre[(size_t)M_TOT * NG];

// ---------------------------------------------------------------------------
// Kernel 0: zero-fill the (B, L, L, 2) output (poisoned by harness)
// ---------------------------------------------------------------------------
__global__ void zero_fill_kernel(float4* __restrict__ out, int n4) {
    int i = blockIdx.x * blockDim.x + threadIdx.x;
    if (i < n4) out[i] = make_float4(0.f, 0.f, 0.f, 0.f);
}

// ---------------------------------------------------------------------------
// Kernel A: g_pre = feats @ W_ih^T + (b_ih + b_hh)
// Classic 128x128x8 SIMT fp32 GEMM, 256 threads, 8x8 microtile.
// Both operands are K-contiguous (NT layout).
// ---------------------------------------------------------------------------
#define BM 128
#define BN 128
#define BK 8

__global__ __launch_bounds__(256) void pre_gemm_kernel(
    const float* __restrict__ A,     // feats  [M_TOT][HH]
    const float* __restrict__ W,     // W_ih   [NG][HH]
    const float* __restrict__ b_ih,
    const float* __restrict__ b_hh,
    const int*   __restrict__ lens)
{
    const int m0 = blockIdx.x * BM;
    const int n0 = blockIdx.y * BN;
    const int b  = m0 / LL;
    const int j0 = m0 % LL;
    // rows j >= lens[b]+3 are never consumed by any emitting cell
    if (j0 >= lens[b] + 3) return;

    __shared__ __align__(16) float As[BK][BM + 4];
    __shared__ __align__(16) float Bs[BK][BN + 4];

    const int t  = threadIdx.x;
    const int tx = t & 15;
    const int ty = t >> 4;

    float acc[8][8];
#pragma unroll
    for (int i = 0; i < 8; i++)
#pragma unroll
        for (int j = 0; j < 8; j++) acc[i][j] = 0.f;

    const int lr = t >> 1;         // row within the 128-row tile
    const int lh = (t & 1) * 4;    // k-offset (0 or 4)

    const float* Aptr = A + (size_t)(m0 + lr) * HH + lh;
    const float* Bptr = W + (size_t)(n0 + lr) * HH + lh;

    for (int k0 = 0; k0 < HH; k0 += BK) {
        float4 av = *(const float4*)(Aptr + k0);
        float4 bv = *(const float4*)(Bptr + k0);
        As[lh + 0][lr] = av.x; As[lh + 1][lr] = av.y;
        As[lh + 2][lr] = av.z; As[lh + 3][lr] = av.w;
        Bs[lh + 0][lr] = bv.x; Bs[lh + 1][lr] = bv.y;
        Bs[lh + 2][lr] = bv.z; Bs[lh + 3][lr] = bv.w;
        __syncthreads();
#pragma unroll
        for (int k = 0; k < BK; k++) {
            float ar[8], br[8];
            *(float4*)(ar)     = *(const float4*)&As[k][ty * 8];
            *(float4*)(ar + 4) = *(const float4*)&As[k][ty * 8 + 4];
            *(float4*)(br)     = *(const float4*)&Bs[k][tx * 8];
            *(float4*)(br + 4) = *(const float4*)&Bs[k][tx * 8 + 4];
#pragma unroll
            for (int i = 0; i < 8; i++)
#pragma unroll
                for (int j = 0; j < 8; j++)
                    acc[i][j] += ar[i] * br[j];
        }
        __syncthreads();
    }

    float bias[8];
#pragma unroll
    for (int j = 0; j < 8; j++) {
        int n = n0 + tx * 8 + j;
        bias[j] = b_ih[n] + b_hh[n];
    }
#pragma unroll
    for (int i = 0; i < 8; i++) {
        int m = m0 + ty * 8 + i;
        float* dst = g_pre + (size_t)m * NG + n0 + tx * 8;
        float4 v0, v1;
        v0.x = acc[i][0] + bias[0]; v0.y = acc[i][1] + bias[1];
        v0.z = acc[i][2] + bias[2]; v0.w = acc[i][3] + bias[3];
        v1.x = acc[i][4] + bias[4]; v1.y = acc[i][5] + bias[5];
        v1.z = acc[i][6] + bias[6]; v1.w = acc[i][7] + bias[7];
        *(float4*)(dst)     = v0;
        *(float4*)(dst + 4) = v1;
    }
}

// ---------------------------------------------------------------------------
// Kernel B: fused 4-step LSTM recurrence + emit + scatter.
// One block = 64 consecutive cells of one batch row (same b).
// Per step: gates(64x512) = g_pre_row + H(64x128) @ W_hh^T, then pointwise
// LSTM; c stays in registers, h round-trips through smem (it is also the
// next step's GEMM A operand). Spans emit when their selected step matures.
// ---------------------------------------------------------------------------
#define MT 64     // cells per block
#define KC 32     // K chunk of W_hh staged in smem
#define HSP (MT + 4)

__device__ __forceinline__ float sigm(float x)  { return 1.f / (1.f + __expf(-x)); }
__device__ __forceinline__ float tanhx(float x) { return 2.f / (1.f + __expf(-2.f * x)) - 1.f; }

__global__ __launch_bounds__(256) void lstm_fused_kernel(
    const float* __restrict__ Whh,   // [NG][HD]
    const float* __restrict__ b_ih,
    const float* __restrict__ b_hh,
    const float* __restrict__ Wtri,  // [2][HD]
    const float* __restrict__ btri,  // [2]
    const int*   __restrict__ lens,
    float*       __restrict__ out)   // [BB][LL][LL][2]
{
    const int blk = blockIdx.x;
    const int b   = blk >> 3;          // LL/MT = 8 blocks per batch row
    const int i0  = (blk & 7) * MT;
    const int len = lens[b];
    if (i0 >= len) return;             // whole block emits nothing

    extern __shared__ __align__(16) float sm[];
    float* Hs    = sm;                         // [HD][HSP]      h (transposed)
    float* Ws    = sm + HD * HSP;              // [KC][NG]       W_hh chunk (transposed)
    float* WtS   = Ws + KC * NG;               // [2][HD]
    float* biasS = WtS + 2 * HD;               // [NG]  b_ih + b_hh (zero-pad rows)

    const int t = threadIdx.x;
    if (t < 2 * HD) WtS[t] = Wtri[t];
    for (int n = t; n < NG; n += 256) biasS[n] = b_ih[n] + b_hh[n];
    __syncthreads();

    const int cg = t & 7;        // cell group: cells cg*8 .. cg*8+7
    const int hg = t >> 3;       // 0..31 : hd  hg*4 .. hg*4+3
    const int cellBase = cg * 8;
    const int hdBase   = hg * 4;

    float c[8][4];
#pragma unroll
    for (int i = 0; i < 8; i++)
#pragma unroll
        for (int j = 0; j < 4; j++) c[i][j] = 0.f;

    int nsteps = len - i0;
    if (nsteps > 4) nsteps = 4;

    const size_t rowBase = (size_t)b * LL;

#pragma unroll 1
    for (int st = 1; st <= 4; st++) {
        // ---- 1) acc init from precomputed input gates (or bias for padding)
        float acc[8][4][4];   // [cell][gate][hd]
#pragma unroll
        for (int ci = 0; ci < 8; ci++) {
            const int i_cell = i0 + cellBase + ci;
            const int j      = i_cell + (st - 1);
            if (j < LL) {
                const float* src = g_pre + (rowBase + j) * NG;
#pragma unroll
                for (int gi = 0; gi < 4; gi++) {
                    float4 v = *(const float4*)(src + gi * HD + hdBase);
                    acc[ci][gi][0] = v.x; acc[ci][gi][1] = v.y;
                    acc[ci][gi][2] = v.z; acc[ci][gi][3] = v.w;
                }
            } else {
#pragma unroll
                for (int gi = 0; gi < 4; gi++) {
                    float4 v = *(const float4*)(biasS + gi * HD + hdBase);
                    acc[ci][gi][0] = v.x; acc[ci][gi][1] = v.y;
                    acc[ci][gi][2] = v.z; acc[ci][gi][3] = v.w;
                }
            }
        }

        // ---- 2) recurrent GEMM: acc += H_prev @ W_hh^T   (skip on step 1, h0=0)
        if (st > 1) {
#pragma unroll 1
            for (int kc = 0; kc < HD; kc += KC) {
                __syncthreads();   // previous chunk readers done
                // stage Ws[kk][n] = W_hh[n][kc+kk]  (coalesced gmem reads)
#pragma unroll
                for (int r = 0; r < 16; r++) {
                    int p = t + 256 * r;       // 0..4095
                    int n = p >> 3;            // 0..511
                    int u = p & 7;             // k sub-offset
                    float4 wv = *(const float4*)(Whh + (size_t)n * HD + kc + 4 * u);
                    Ws[(4 * u + 0) * NG + n] = wv.x;
                    Ws[(4 * u + 1) * NG + n] = wv.y;
                    Ws[(4 * u + 2) * NG + n] = wv.z;
                    Ws[(4 * u + 3) * NG + n] = wv.w;
                }
                __syncthreads();
#pragma unroll 2
                for (int kk = 0; kk < KC; kk++) {
                    float hv[8];
                    const float* hrow = Hs + (kc + kk) * HSP + cellBase;
                    *(float4*)(hv)     = *(const float4*)(hrow);
                    *(float4*)(hv + 4) = *(const float4*)(hrow + 4);
#pragma unroll
                    for (int gi = 0; gi < 4; gi++) {
                        float wv4[4];
                        *(float4*)wv4 = *(const float4*)(Ws + kk * NG + gi * HD + hdBase);
#pragma unroll
                        for (int ci = 0; ci < 8; ci++)
#pragma unroll
                            for (int hh = 0; hh < 4; hh++)
                                acc[ci][gi][hh] += hv[ci] * wv4[hh];
                    }
                }
            }
        }

        // ---- 3) pointwise LSTM (torch gate order i, f, g, o)
        float hnew[8][4];
#pragma unroll
        for (int ci = 0; ci < 8; ci++)
#pragma unroll
            for (int hh = 0; hh < 4; hh++) {
                float ig = sigm(acc[ci][0][hh]);
                float fg = sigm(acc[ci][1][hh]);
                float gg = tanhx(acc[ci][2][hh]);
                float og = sigm(acc[ci][3][hh]);
                float cn = fg * c[ci][hh] + ig * gg;
                c[ci][hh] = cn;
                hnew[ci][hh] = og * tanhx(cn);
            }
        __syncthreads();   // all reads of old Hs done
#pragma unroll
        for (int ci = 0; ci < 8; ci++)
#pragma unroll
            for (int hh = 0; hh < 4; hh++)
                Hs[(hdBase + hh) * HSP + cellBase + ci] = hnew[ci][hh];
        __syncthreads();

        // ---- 4) emit spans whose selected step == st
        {
            const int cc = t & 63;         // local cell
            const int w  = (t >> 6) + 1;   // span width 1..4
            const int i_cell = i0 + cc;
            const int rem = len - i_cell;
            const int j   = i_cell + w - 1;
            if (rem >= 1 && j < LL && min(rem, w) == st) {
                float s0 = btri[0], s1 = btri[1];
#pragma unroll 8
                for (int k = 0; k < HD; k++) {
                    float hv = Hs[k * HSP + cc];
                    s0 += hv * WtS[k];
                    s1 += hv * WtS[HD + k];
                }
                size_t o = (((size_t)b * LL + i_cell) * LL + j) * 2;
                out[o]     = s0;
                out[o + 1] = s1;
            }
        }
        if (st >= nsteps) break;
    }
}

// ---------------------------------------------------------------------------
extern "C" void kernel_launch(void* const* d_in, const int* in_sizes, int n_in,
                              void* d_out, int out_size) {
    const float* feats = (const float*)d_in[0];
    const float* W_ih  = (const float*)d_in[1];
    const float* W_hh  = (const float*)d_in[2];
    const float* b_ih  = (const float*)d_in[3];
    const float* b_hh  = (const float*)d_in[4];
    const float* W_tri = (const float*)d_in[5];
    const float* b_tri = (const float*)d_in[6];
    const int*   lens  = (const int*)d_in[7];
    float* out = (float*)d_out;

    // 0) zero the 134 MB output
    int n4 = out_size / 4;   // 8,388,608 float4
    zero_fill_kernel<<<(n4 + 255) / 256, 256>>>((float4*)out, n4);

    // A) input projection GEMM into g_pre
    dim3 gA(M_TOT / BM, NG / BN);
    pre_gemm_kernel<<<gA, 256>>>(feats, W_ih, b_ih, b_hh, lens);

    // B) fused recurrence + emit
    const int smemB = (HD * HSP + KC * NG + 2 * HD + NG) * (int)sizeof(float);
    static int attr_done = 0;
    cudaFuncSetAttribute((const void*)lstm_fused_kernel,
                         cudaFuncAttributeMaxDynamicSharedMemorySize, smemB);
    (void)attr_done;
    lstm_fused_kernel<<<M_TOT / MT, 256, smemB>>>(W_hh, b_ih, b_hh,
                                                  W_tri, b_tri, lens, out);
}